// round 12
// baseline (speedup 1.0000x reference)
#include <cuda_runtime.h>
#include <cstdint>

// GraphConvolutionSparse: out = adj @ (inputs @ W)
//   inputs [16384,512] f32, adj [16384,16384] f32, weights [512,128] f32 -> out [16384,128] f32
// Warp-specialized TF32 mma.sync GEMM, BK=64, cross-tile software pipeline.
//   producers (4 warps): cp.async raw f32 tiles
//   consumers (8 warps): ldmatrix/LDS -> (cvt.rna A; B pre-rounded) -> mma
//     - empty[s] arrives right after the tile's last smem read (kq==6)
//     - next tile's first fragments prefetched before the last mma burst

#define N_ROWS 16384
#define D_IN   512
#define D_OUT  128

__device__ float g_X[N_ROWS * D_OUT];   // X = inputs @ W (tf32-rounded bits)

namespace {

constexpr int BM = 128, BN = 128, BK = 64;
constexpr int AS = BK + 4;     // 68 floats/row (A tile)
constexpr int BS = BN + 8;     // 136 floats/row (B tile)
constexpr int A_SZ = BM * AS;  // 8704 floats
constexpr int B_SZ = BK * BS;  // 8704 floats
constexpr int BUF  = A_SZ + B_SZ;          // 17408 floats / stage
constexpr int NSTAGE = 3;
constexpr int CTRL_F = 256;                // 1024 B control region (mbarriers)
constexpr int SMEM_BYTES = (CTRL_F + NSTAGE * BUF) * 4;   // 209920 B

constexpr int NCONS = 8;                   // consumer warps
constexpr int NPROD_THREADS = 128;         // 4 producer warps
constexpr int NTHREADS = NCONS * 32 + NPROD_THREADS;  // 384

constexpr int F_CVT_B   = 1;  // cvt B fragments in consumer (B not pre-rounded)
constexpr int F_ROUND_C = 2;  // round C to tf32 bits in epilogue

__device__ __forceinline__ void cp_async16(uint32_t dst, const void* src) {
    asm volatile("cp.async.cg.shared.global [%0], [%1], 16;\n" :: "r"(dst), "l"(src));
}

__device__ __forceinline__ uint32_t f2tf32(float f) {
    uint32_t r;
    asm("cvt.rna.tf32.f32 %0, %1;" : "=r"(r) : "f"(f));
    return r;
}

__device__ __forceinline__ uint32_t cvt_bits(uint32_t raw) {
    return f2tf32(__uint_as_float(raw));
}

__device__ __forceinline__ void mbar_init(uint32_t addr, uint32_t cnt) {
    asm volatile("mbarrier.init.shared.b64 [%0], %1;" :: "r"(addr), "r"(cnt) : "memory");
}

__device__ __forceinline__ void mbar_arrive(uint32_t addr) {
    asm volatile("mbarrier.arrive.release.cta.shared::cta.b64 _, [%0];"
                 :: "r"(addr) : "memory");
}

__device__ __forceinline__ void mbar_wait(uint32_t mbar, uint32_t parity) {
    asm volatile(
        "{\n\t.reg .pred P1;\n\t"
        "LWAIT_%=:\n\t"
        "mbarrier.try_wait.parity.acquire.cta.shared::cta.b64 P1, [%0], %1, 0x989680;\n\t"
        "@P1 bra LDONE_%=;\n\t"
        "bra LWAIT_%=;\n\t"
        "LDONE_%=:\n\t}"
        :: "r"(mbar), "r"(parity) : "memory");
}

// ldmatrix x4 on f32 data: each m8n8.b16 tile == 8 rows x 4 f32 (16B rows);
// thread t gets element (t/4, t%4) of each tile.
__device__ __forceinline__ void ldsm_x4(uint32_t& r0, uint32_t& r1,
                                        uint32_t& r2, uint32_t& r3, uint32_t addr) {
    asm volatile("ldmatrix.sync.aligned.m8n8.x4.shared.b16 {%0,%1,%2,%3}, [%4];"
                 : "=r"(r0), "=r"(r1), "=r"(r2), "=r"(r3) : "r"(addr));
}

__device__ __forceinline__ void mma_tf32(float& c0, float& c1, float& c2, float& c3,
                                         uint32_t a0, uint32_t a1, uint32_t a2, uint32_t a3,
                                         uint32_t b0, uint32_t b1) {
    asm volatile(
        "mma.sync.aligned.m16n8k8.row.col.f32.tf32.tf32.f32 "
        "{%0,%1,%2,%3}, {%4,%5,%6,%7}, {%8,%9}, {%0,%1,%2,%3};"
        : "+f"(c0), "+f"(c1), "+f"(c2), "+f"(c3)
        : "r"(a0), "r"(a1), "r"(a2), "r"(a3), "r"(b0), "r"(b1));
}

} // namespace

// C[M,BN] = A[M,K] @ B[K,BN]; A row-major (lda), B row-major (BN). grid.x=M/BM.
__global__ __launch_bounds__(NTHREADS, 1)
void gemm_ws_tf32(float* __restrict__ C, const float* __restrict__ A,
                  const float* __restrict__ B, int K, size_t lda, int flags) {
    extern __shared__ __align__(1024) float smem[];
    const int tid = threadIdx.x, wid = tid >> 5, lane = tid & 31;
    const int m0 = blockIdx.x * BM;
    const uint32_t sbase = (uint32_t)__cvta_generic_to_shared(smem);
    const uint32_t dbase = sbase + CTRL_F * 4;
    const int KT = K / BK;

    if (tid == 0) {
        #pragma unroll
        for (int s = 0; s < NSTAGE; ++s) {
            mbar_init(sbase + 16 * s,     NPROD_THREADS);  // full (async-group arrive)
            mbar_init(sbase + 16 * s + 8, NCONS);          // empty
        }
    }
    __syncthreads();

    if (wid >= NCONS) {
        // ---------------- producers (4 warps, cp.async only) ----------------
        const int pt = tid - NCONS * 32;          // 0..127
        const float* Ab = A + (size_t)m0 * lda;

        for (int kt = 0; kt < KT; ++kt) {
            const int s = kt % NSTAGE;
            if (kt >= NSTAGE)
                mbar_wait(sbase + 16 * s + 8, (uint32_t)((kt / NSTAGE - 1) & 1));
            const float* Ak = Ab + (size_t)kt * BK;
            const float* Bk = B + (size_t)(kt * BK) * BN;
            const uint32_t dA = dbase + (uint32_t)(s * BUF) * 4u;
            const uint32_t dB = dA + (uint32_t)A_SZ * 4u;
            // A tile: 128 rows x 16 chunks; chunk c -> (row=c>>4, ch=c&15)
            #pragma unroll
            for (int i = 0; i < 16; ++i) {
                const int c = i * 128 + pt;
                const int row = c >> 4, ch = c & 15;
                cp_async16(dA + (uint32_t)(row * AS + ch * 4) * 4u,
                           Ak + (size_t)row * lda + ch * 4);
            }
            // B tile: 64 rows x 32 chunks; chunk c -> (row=c>>5, ch=c&31)
            #pragma unroll
            for (int i = 0; i < 16; ++i) {
                const int c = i * 128 + pt;
                const int row = c >> 5, ch = c & 31;
                cp_async16(dB + (uint32_t)(row * BS + ch * 4) * 4u,
                           Bk + (size_t)row * BN + ch * 4);
            }
            asm volatile("cp.async.mbarrier.arrive.noinc.shared::cta.b64 [%0];"
                         :: "r"(sbase + 16 * s) : "memory");
        }
    } else {
        // ------ consumers (8 warps): cross-tile pipelined; cvt A (B optional) ------
        const int wr = wid >> 2;              // 0..1 (64 rows each)
        const int wc = wid & 3;               // 0..3 (32 cols each)
        const int gid = lane >> 2, tig = lane & 3;
        const int lm_row = wr * 64 + (lane & 7) + ((lane >> 3) & 1) * 8;
        const int lm_k   = ((lane >> 3) >> 1) * 4;
        const bool cvtB = (flags & F_CVT_B) != 0;

        float acc[4][4][4];
        #pragma unroll
        for (int mi = 0; mi < 4; ++mi)
            #pragma unroll
            for (int ni = 0; ni < 4; ++ni)
                #pragma unroll
                for (int r = 0; r < 4; ++r) acc[mi][ni][r] = 0.0f;

        uint32_t a[2][4][4], b[2][4][2];
        uint32_t aBase;
        const uint32_t* Bu;

        auto set_tile = [&](int s) {
            aBase = dbase + (uint32_t)(s * BUF + lm_row * AS + lm_k) * 4u;
            Bu = (const uint32_t*)(smem + CTRL_F + s * BUF + A_SZ);
        };

        auto load_frag = [&](int kk, int d) {
            #pragma unroll
            for (int mi = 0; mi < 4; ++mi)
                ldsm_x4(a[d][mi][0], a[d][mi][1], a[d][mi][2], a[d][mi][3],
                        aBase + (uint32_t)(mi * 16 * AS + kk) * 4u);
            #pragma unroll
            for (int ni = 0; ni < 4; ++ni) {
                const int c = wc * 32 + ni * 8 + gid;
                b[d][ni][0] = Bu[(kk + tig) * BS + c];
                b[d][ni][1] = Bu[(kk + tig + 4) * BS + c];
            }
        };

        // prologue: tile 0, fragment 0 -> buffer 0
        mbar_wait(sbase + 0, 0u);
        set_tile(0);
        load_frag(0, 0);

        for (int kt = 0; kt < KT; ++kt) {
            const int s = kt % NSTAGE;
            #pragma unroll
            for (int kq = 0; kq < BK / 8; ++kq) {
                const int d = kq & 1;
                if (kq < BK / 8 - 1) {
                    load_frag((kq + 1) * 8, d ^ 1);
                    if (kq == BK / 8 - 2) {
                        // all smem reads of this tile issued -> release the stage
                        __syncwarp();
                        if (lane == 0) mbar_arrive(sbase + 16 * s + 8);
                    }
                } else if (kt + 1 < KT) {
                    // prefetch next tile's first fragments before the last burst
                    const int s2 = (kt + 1) % NSTAGE;
                    mbar_wait(sbase + 16 * s2, (uint32_t)(((kt + 1) / NSTAGE) & 1));
                    set_tile(s2);
                    load_frag(0, d ^ 1);
                }
                // A fragments: round-to-nearest tf32 (required for accuracy)
                #pragma unroll
                for (int mi = 0; mi < 4; ++mi)
                    #pragma unroll
                    for (int j = 0; j < 4; ++j)
                        a[d][mi][j] = cvt_bits(a[d][mi][j]);
                if (cvtB) {
                    #pragma unroll
                    for (int ni = 0; ni < 4; ++ni) {
                        b[d][ni][0] = cvt_bits(b[d][ni][0]);
                        b[d][ni][1] = cvt_bits(b[d][ni][1]);
                    }
                }
                #pragma unroll
                for (int mi = 0; mi < 4; ++mi)
                    #pragma unroll
                    for (int ni = 0; ni < 4; ++ni)
                        mma_tf32(acc[mi][ni][0], acc[mi][ni][1], acc[mi][ni][2], acc[mi][ni][3],
                                 a[d][mi][0], a[d][mi][1], a[d][mi][2], a[d][mi][3],
                                 b[d][ni][0], b[d][ni][1]);
            }
        }

        // epilogue (optionally round C to tf32 bits for the pre-rounded X path)
        const bool roundC = (flags & F_ROUND_C) != 0;
        #pragma unroll
        for (int mi = 0; mi < 4; ++mi) {
            #pragma unroll
            for (int ni = 0; ni < 4; ++ni) {
                float v0 = acc[mi][ni][0], v1 = acc[mi][ni][1];
                float v2 = acc[mi][ni][2], v3 = acc[mi][ni][3];
                if (roundC) {
                    v0 = __uint_as_float(f2tf32(v0));
                    v1 = __uint_as_float(f2tf32(v1));
                    v2 = __uint_as_float(f2tf32(v2));
                    v3 = __uint_as_float(f2tf32(v3));
                }
                const int row = m0 + wr * 64 + mi * 16 + gid;
                const int col = wc * 32 + ni * 8 + tig * 2;
                *(float2*)(C + (size_t)row * BN + col) = make_float2(v0, v1);
                *(float2*)(C + (size_t)(row + 8) * BN + col) = make_float2(v2, v3);
            }
        }
    }
}

extern "C" void kernel_launch(void* const* d_in, const int* in_sizes, int n_in,
                              void* d_out, int out_size) {
    const float* inputs  = (const float*)d_in[0];   // [16384, 512]
    const float* adj     = (const float*)d_in[1];   // [16384, 16384]
    const float* weights = (const float*)d_in[2];   // [512, 128]
    float* out = (float*)d_out;                     // [16384, 128]
    (void)in_sizes; (void)n_in; (void)out_size;

    cudaFuncSetAttribute(gemm_ws_tf32,
                         cudaFuncAttributeMaxDynamicSharedMemorySize, SMEM_BYTES);

    float* X = nullptr;
    cudaGetSymbolAddress((void**)&X, g_X);

    // G1: X = inputs @ W   (K=512): cvt B (raw weights), round X on output
    gemm_ws_tf32<<<N_ROWS / BM, NTHREADS, SMEM_BYTES>>>(
        X, inputs, weights, D_IN, D_IN, F_CVT_B | F_ROUND_C);
    // G2: out = adj @ X    (K=16384): B pre-rounded, plain f32 output
    gemm_ws_tf32<<<N_ROWS / BM, NTHREADS, SMEM_BYTES>>>(
        out, adj, X, N_ROWS, N_ROWS, 0);
}

// round 13
// speedup vs baseline: 2.2256x; 2.2256x over previous
#include <cuda_runtime.h>
#include <cstdint>

// GraphConvolutionSparse: out = adj @ (inputs @ W)
//   inputs [16384,512] f32, adj [16384,16384] f32, weights [512,128] f32 -> out [16384,128] f32
// Warp-specialized TF32 mma.sync GEMM, BM=64 / 2 CTAs per SM for stall overlap.
//   producers (2 warps): cp.async raw f32 tiles
//   consumers (4 warps): ldmatrix/LDS -> (cvt.rna A; B pre-rounded) -> mma

#define N_ROWS 16384
#define D_IN   512
#define D_OUT  128

__device__ float g_X[N_ROWS * D_OUT];   // X = inputs @ W (tf32-rounded bits)

namespace {

constexpr int BM = 64, BN = 128, BK = 64;
constexpr int AS = BK + 4;     // 68 floats/row (A tile)
constexpr int BS = BN + 8;     // 136 floats/row (B tile)
constexpr int A_SZ = BM * AS;  // 4352 floats
constexpr int B_SZ = BK * BS;  // 8704 floats
constexpr int BUF  = A_SZ + B_SZ;          // 13056 floats / stage
constexpr int NSTAGE = 2;
constexpr int CTRL_F = 256;                // 1024 B control region (mbarriers)
constexpr int SMEM_BYTES = (CTRL_F + NSTAGE * BUF) * 4;   // 105472 B -> 2 CTAs/SM

constexpr int NCONS = 4;                   // consumer warps
constexpr int NPROD_THREADS = 64;          // 2 producer warps
constexpr int NTHREADS = NCONS * 32 + NPROD_THREADS;  // 192

constexpr int F_CVT_B   = 1;  // cvt B fragments in consumer (B not pre-rounded)
constexpr int F_ROUND_C = 2;  // round C to tf32 bits in epilogue

__device__ __forceinline__ void cp_async16(uint32_t dst, const void* src) {
    asm volatile("cp.async.cg.shared.global [%0], [%1], 16;\n" :: "r"(dst), "l"(src));
}

__device__ __forceinline__ uint32_t f2tf32(float f) {
    uint32_t r;
    asm("cvt.rna.tf32.f32 %0, %1;" : "=r"(r) : "f"(f));
    return r;
}

__device__ __forceinline__ uint32_t cvt_bits(uint32_t raw) {
    return f2tf32(__uint_as_float(raw));
}

__device__ __forceinline__ void mbar_init(uint32_t addr, uint32_t cnt) {
    asm volatile("mbarrier.init.shared.b64 [%0], %1;" :: "r"(addr), "r"(cnt) : "memory");
}

__device__ __forceinline__ void mbar_arrive(uint32_t addr) {
    asm volatile("mbarrier.arrive.release.cta.shared::cta.b64 _, [%0];"
                 :: "r"(addr) : "memory");
}

__device__ __forceinline__ void mbar_wait(uint32_t mbar, uint32_t parity) {
    asm volatile(
        "{\n\t.reg .pred P1;\n\t"
        "LWAIT_%=:\n\t"
        "mbarrier.try_wait.parity.acquire.cta.shared::cta.b64 P1, [%0], %1, 0x989680;\n\t"
        "@P1 bra LDONE_%=;\n\t"
        "bra LWAIT_%=;\n\t"
        "LDONE_%=:\n\t}"
        :: "r"(mbar), "r"(parity) : "memory");
}

// ldmatrix x4 on f32 data: each m8n8.b16 tile == 8 rows x 4 f32 (16B rows);
// thread t gets element (t/4, t%4) of each tile.
__device__ __forceinline__ void ldsm_x4(uint32_t& r0, uint32_t& r1,
                                        uint32_t& r2, uint32_t& r3, uint32_t addr) {
    asm volatile("ldmatrix.sync.aligned.m8n8.x4.shared.b16 {%0,%1,%2,%3}, [%4];"
                 : "=r"(r0), "=r"(r1), "=r"(r2), "=r"(r3) : "r"(addr));
}

__device__ __forceinline__ void mma_tf32(float& c0, float& c1, float& c2, float& c3,
                                         uint32_t a0, uint32_t a1, uint32_t a2, uint32_t a3,
                                         uint32_t b0, uint32_t b1) {
    asm volatile(
        "mma.sync.aligned.m16n8k8.row.col.f32.tf32.tf32.f32 "
        "{%0,%1,%2,%3}, {%4,%5,%6,%7}, {%8,%9}, {%0,%1,%2,%3};"
        : "+f"(c0), "+f"(c1), "+f"(c2), "+f"(c3)
        : "r"(a0), "r"(a1), "r"(a2), "r"(a3), "r"(b0), "r"(b1));
}

} // namespace

// C[M,BN] = A[M,K] @ B[K,BN]; A row-major (lda), B row-major (BN). grid.x=M/BM.
__global__ __launch_bounds__(NTHREADS, 2)
void gemm_ws_tf32(float* __restrict__ C, const float* __restrict__ A,
                  const float* __restrict__ B, int K, size_t lda, int flags) {
    extern __shared__ __align__(1024) float smem[];
    const int tid = threadIdx.x, wid = tid >> 5, lane = tid & 31;
    const int m0 = blockIdx.x * BM;
    const uint32_t sbase = (uint32_t)__cvta_generic_to_shared(smem);
    const uint32_t dbase = sbase + CTRL_F * 4;
    const int KT = K / BK;

    if (tid == 0) {
        #pragma unroll
        for (int s = 0; s < NSTAGE; ++s) {
            mbar_init(sbase + 16 * s,     NPROD_THREADS);  // full (async-group arrive)
            mbar_init(sbase + 16 * s + 8, NCONS);          // empty
        }
    }
    __syncthreads();

    if (wid >= NCONS) {
        // ---------------- producers (2 warps, cp.async only) ----------------
        const int pt = tid - NCONS * 32;          // 0..63
        const float* Ab = A + (size_t)m0 * lda;

        for (int kt = 0; kt < KT; ++kt) {
            const int s = kt & (NSTAGE - 1);
            if (kt >= NSTAGE)
                mbar_wait(sbase + 16 * s + 8, (uint32_t)(((kt >> 1) - 1) & 1));
            const float* Ak = Ab + (size_t)kt * BK;
            const float* Bk = B + (size_t)(kt * BK) * BN;
            const uint32_t dA = dbase + (uint32_t)(s * BUF) * 4u;
            const uint32_t dB = dA + (uint32_t)A_SZ * 4u;
            // A tile: 64 rows x 16 chunks = 1024 chunks; c -> (row=c>>4, ch=c&15)
            #pragma unroll
            for (int i = 0; i < 16; ++i) {
                const int c = i * 64 + pt;
                const int row = c >> 4, ch = c & 15;
                cp_async16(dA + (uint32_t)(row * AS + ch * 4) * 4u,
                           Ak + (size_t)row * lda + ch * 4);
            }
            // B tile: 64 rows x 32 chunks = 2048 chunks; c -> (row=c>>5, ch=c&31)
            #pragma unroll
            for (int i = 0; i < 32; ++i) {
                const int c = i * 64 + pt;
                const int row = c >> 5, ch = c & 31;
                cp_async16(dB + (uint32_t)(row * BS + ch * 4) * 4u,
                           Bk + (size_t)row * BN + ch * 4);
            }
            asm volatile("cp.async.mbarrier.arrive.noinc.shared::cta.b64 [%0];"
                         :: "r"(sbase + 16 * s) : "memory");
        }
    } else {
        // ---- consumers (4 warps, 32x64 block each): ld -> cvt.rna A -> mma ----
        const int wr = wid >> 1;              // 0..1 (32 rows each)
        const int wc = wid & 1;               // 0..1 (64 cols each)
        const int gid = lane >> 2, tig = lane & 3;
        const int lm_row = wr * 32 + (lane & 7) + ((lane >> 3) & 1) * 8;
        const int lm_k   = ((lane >> 3) >> 1) * 4;
        const bool cvtB = (flags & F_CVT_B) != 0;

        float acc[2][8][4];
        #pragma unroll
        for (int mi = 0; mi < 2; ++mi)
            #pragma unroll
            for (int ni = 0; ni < 8; ++ni)
                #pragma unroll
                for (int r = 0; r < 4; ++r) acc[mi][ni][r] = 0.0f;

        uint32_t a[2][2][4], b[2][8][2];

        for (int kt = 0; kt < KT; ++kt) {
            const int s = kt & (NSTAGE - 1);
            mbar_wait(sbase + 16 * s, (uint32_t)((kt >> 1) & 1));

            const uint32_t aBase = dbase + (uint32_t)(s * BUF + lm_row * AS + lm_k) * 4u;
            const uint32_t* Bu = (const uint32_t*)(smem + CTRL_F + s * BUF + A_SZ);

            auto load_frag = [&](int kk, int d) {
                #pragma unroll
                for (int mi = 0; mi < 2; ++mi)
                    ldsm_x4(a[d][mi][0], a[d][mi][1], a[d][mi][2], a[d][mi][3],
                            aBase + (uint32_t)(mi * 16 * AS + kk) * 4u);
                #pragma unroll
                for (int ni = 0; ni < 8; ++ni) {
                    const int c = wc * 64 + ni * 8 + gid;
                    b[d][ni][0] = Bu[(kk + tig) * BS + c];
                    b[d][ni][1] = Bu[(kk + tig + 4) * BS + c];
                }
            };

            load_frag(0, 0);
            #pragma unroll
            for (int kq = 0; kq < BK / 8; ++kq) {
                const int d = kq & 1;
                if (kq < BK / 8 - 1) {
                    load_frag((kq + 1) * 8, d ^ 1);
                    if (kq == BK / 8 - 2) {
                        // all smem reads of this tile issued -> release the stage
                        __syncwarp();
                        if (lane == 0) mbar_arrive(sbase + 16 * s + 8);
                    }
                }
                // A fragments: round-to-nearest tf32 (required for accuracy)
                #pragma unroll
                for (int mi = 0; mi < 2; ++mi)
                    #pragma unroll
                    for (int j = 0; j < 4; ++j)
                        a[d][mi][j] = cvt_bits(a[d][mi][j]);
                if (cvtB) {
                    #pragma unroll
                    for (int ni = 0; ni < 8; ++ni) {
                        b[d][ni][0] = cvt_bits(b[d][ni][0]);
                        b[d][ni][1] = cvt_bits(b[d][ni][1]);
                    }
                }
                #pragma unroll
                for (int mi = 0; mi < 2; ++mi)
                    #pragma unroll
                    for (int ni = 0; ni < 8; ++ni)
                        mma_tf32(acc[mi][ni][0], acc[mi][ni][1], acc[mi][ni][2], acc[mi][ni][3],
                                 a[d][mi][0], a[d][mi][1], a[d][mi][2], a[d][mi][3],
                                 b[d][ni][0], b[d][ni][1]);
            }
        }

        // epilogue (optionally round C to tf32 bits for the pre-rounded X path)
        const bool roundC = (flags & F_ROUND_C) != 0;
        #pragma unroll
        for (int mi = 0; mi < 2; ++mi) {
            #pragma unroll
            for (int ni = 0; ni < 8; ++ni) {
                float v0 = acc[mi][ni][0], v1 = acc[mi][ni][1];
                float v2 = acc[mi][ni][2], v3 = acc[mi][ni][3];
                if (roundC) {
                    v0 = __uint_as_float(f2tf32(v0));
                    v1 = __uint_as_float(f2tf32(v1));
                    v2 = __uint_as_float(f2tf32(v2));
                    v3 = __uint_as_float(f2tf32(v3));
                }
                const int row = m0 + wr * 32 + mi * 16 + gid;
                const int col = wc * 64 + ni * 8 + tig * 2;
                *(float2*)(C + (size_t)row * BN + col) = make_float2(v0, v1);
                *(float2*)(C + (size_t)(row + 8) * BN + col) = make_float2(v2, v3);
            }
        }
    }
}

extern "C" void kernel_launch(void* const* d_in, const int* in_sizes, int n_in,
                              void* d_out, int out_size) {
    const float* inputs  = (const float*)d_in[0];   // [16384, 512]
    const float* adj     = (const float*)d_in[1];   // [16384, 16384]
    const float* weights = (const float*)d_in[2];   // [512, 128]
    float* out = (float*)d_out;                     // [16384, 128]
    (void)in_sizes; (void)n_in; (void)out_size;

    cudaFuncSetAttribute(gemm_ws_tf32,
                         cudaFuncAttributeMaxDynamicSharedMemorySize, SMEM_BYTES);

    float* X = nullptr;
    cudaGetSymbolAddress((void**)&X, g_X);

    // G1: X = inputs @ W   (K=512): cvt B (raw weights), round X on output
    gemm_ws_tf32<<<N_ROWS / BM, NTHREADS, SMEM_BYTES>>>(
        X, inputs, weights, D_IN, D_IN, F_CVT_B | F_ROUND_C);
    // G2: out = adj @ X    (K=16384): B pre-rounded, plain f32 output
    gemm_ws_tf32<<<N_ROWS / BM, NTHREADS, SMEM_BYTES>>>(
        out, adj, X, N_ROWS, N_ROWS, 0);
}

// round 14
// speedup vs baseline: 2.2324x; 1.0031x over previous
#include <cuda_runtime.h>
#include <cstdint>

// GraphConvolutionSparse: out = adj @ (inputs @ W)
//   inputs [16384,512] f32, adj [16384,16384] f32, weights [512,128] f32 -> out [16384,128] f32
// Warp-specialized TF32 mma.sync GEMM, BM=64 / 2 CTAs per SM.
// B is N-MAJOR ([BN,K]): B fragments load via ldmatrix (4 ldsm vs 16 LDS per kq).
//   G1: X^T = (inputs @ W)^T, tf32-pre-rounded  (B = W^T via tiny transpose)
//   G2: out = adj @ X using X^T as N-major B, no B cvt needed

#define N_ROWS 16384
#define D_IN   512
#define D_OUT  128

__device__ float g_XT[D_OUT * N_ROWS];  // X^T [128,16384], tf32-rounded bits
__device__ float g_WT[D_OUT * D_IN];    // W^T [128,512]

namespace {

constexpr int BM = 64, BN = 128, BK = 64;
constexpr int AS  = BK + 4;    // 68 floats/row (A tile, K-major)
constexpr int BTS = BK + 4;    // 68 floats/row (B tile, N-major: BN rows x BK)
constexpr int A_SZ = BM * AS;  // 4352 floats
constexpr int B_SZ = BN * BTS; // 8704 floats
constexpr int BUF  = A_SZ + B_SZ;          // 13056 floats / stage
constexpr int NSTAGE = 2;
constexpr int CTRL_F = 256;                // 1024 B control region (mbarriers)
constexpr int SMEM_BYTES = (CTRL_F + NSTAGE * BUF) * 4;   // 105472 B -> 2 CTAs/SM

constexpr int NCONS = 4;                   // consumer warps
constexpr int NPROD_THREADS = 64;          // 2 producer warps
constexpr int NTHREADS = NCONS * 32 + NPROD_THREADS;  // 192

constexpr int F_CVT_B  = 1;  // cvt B fragments in consumer (B not pre-rounded)
constexpr int F_XT_OUT = 2;  // epilogue: round C to tf32 bits and store transposed

__device__ __forceinline__ void cp_async16(uint32_t dst, const void* src) {
    asm volatile("cp.async.cg.shared.global [%0], [%1], 16;\n" :: "r"(dst), "l"(src));
}

__device__ __forceinline__ uint32_t f2tf32(float f) {
    uint32_t r;
    asm("cvt.rna.tf32.f32 %0, %1;" : "=r"(r) : "f"(f));
    return r;
}

__device__ __forceinline__ uint32_t cvt_bits(uint32_t raw) {
    return f2tf32(__uint_as_float(raw));
}

__device__ __forceinline__ void mbar_init(uint32_t addr, uint32_t cnt) {
    asm volatile("mbarrier.init.shared.b64 [%0], %1;" :: "r"(addr), "r"(cnt) : "memory");
}

__device__ __forceinline__ void mbar_arrive(uint32_t addr) {
    asm volatile("mbarrier.arrive.release.cta.shared::cta.b64 _, [%0];"
                 :: "r"(addr) : "memory");
}

__device__ __forceinline__ void mbar_wait(uint32_t mbar, uint32_t parity) {
    asm volatile(
        "{\n\t.reg .pred P1;\n\t"
        "LWAIT_%=:\n\t"
        "mbarrier.try_wait.parity.acquire.cta.shared::cta.b64 P1, [%0], %1, 0x989680;\n\t"
        "@P1 bra LDONE_%=;\n\t"
        "bra LWAIT_%=;\n\t"
        "LDONE_%=:\n\t}"
        :: "r"(mbar), "r"(parity) : "memory");
}

// ldmatrix x4 on f32 data: each m8n8.b16 tile == 8 rows x 4 f32 (16B rows);
// thread t gets element (t/4, t%4) of each tile.
__device__ __forceinline__ void ldsm_x4(uint32_t& r0, uint32_t& r1,
                                        uint32_t& r2, uint32_t& r3, uint32_t addr) {
    asm volatile("ldmatrix.sync.aligned.m8n8.x4.shared.b16 {%0,%1,%2,%3}, [%4];"
                 : "=r"(r0), "=r"(r1), "=r"(r2), "=r"(r3) : "r"(addr));
}

__device__ __forceinline__ void mma_tf32(float& c0, float& c1, float& c2, float& c3,
                                         uint32_t a0, uint32_t a1, uint32_t a2, uint32_t a3,
                                         uint32_t b0, uint32_t b1) {
    asm volatile(
        "mma.sync.aligned.m16n8k8.row.col.f32.tf32.tf32.f32 "
        "{%0,%1,%2,%3}, {%4,%5,%6,%7}, {%8,%9}, {%0,%1,%2,%3};"
        : "+f"(c0), "+f"(c1), "+f"(c2), "+f"(c3)
        : "r"(a0), "r"(a1), "r"(a2), "r"(a3), "r"(b0), "r"(b1));
}

} // namespace

// C[M,BN] = A[M,K] @ B^T, A row-major (lda), B is [BN,K] N-major (ldb).
// Normal store: C row-major with stride ldc(=BN). F_XT_OUT: C[col*ldc+row], rounded.
__global__ __launch_bounds__(NTHREADS, 2)
void gemm_ws_tf32(float* __restrict__ C, const float* __restrict__ A,
                  const float* __restrict__ B, int K,
                  size_t lda, size_t ldb, size_t ldc, int flags) {
    extern __shared__ __align__(1024) float smem[];
    const int tid = threadIdx.x, wid = tid >> 5, lane = tid & 31;
    const int m0 = blockIdx.x * BM;
    const uint32_t sbase = (uint32_t)__cvta_generic_to_shared(smem);
    const uint32_t dbase = sbase + CTRL_F * 4;
    const int KT = K / BK;

    if (tid == 0) {
        #pragma unroll
        for (int s = 0; s < NSTAGE; ++s) {
            mbar_init(sbase + 16 * s,     NPROD_THREADS);  // full (async-group arrive)
            mbar_init(sbase + 16 * s + 8, NCONS);          // empty
        }
    }
    __syncthreads();

    if (wid >= NCONS) {
        // ---------------- producers (2 warps, cp.async only) ----------------
        const int pt = tid - NCONS * 32;          // 0..63
        const float* Ab = A + (size_t)m0 * lda;

        for (int kt = 0; kt < KT; ++kt) {
            const int s = kt & (NSTAGE - 1);
            if (kt >= NSTAGE)
                mbar_wait(sbase + 16 * s + 8, (uint32_t)(((kt >> 1) - 1) & 1));
            const float* Ak = Ab + (size_t)kt * BK;
            const float* Bk = B + (size_t)kt * BK;
            const uint32_t dA = dbase + (uint32_t)(s * BUF) * 4u;
            const uint32_t dB = dA + (uint32_t)A_SZ * 4u;
            // A tile: 64 rows x 16 chunks = 1024; c -> (row=c>>4, ch=c&15)
            #pragma unroll
            for (int i = 0; i < 16; ++i) {
                const int c = i * 64 + pt;
                const int row = c >> 4, ch = c & 15;
                cp_async16(dA + (uint32_t)(row * AS + ch * 4) * 4u,
                           Ak + (size_t)row * lda + ch * 4);
            }
            // B tile (N-major): 128 rows x 16 chunks = 2048; c -> (row=c>>4, ch=c&15)
            #pragma unroll
            for (int i = 0; i < 32; ++i) {
                const int c = i * 64 + pt;
                const int row = c >> 4, ch = c & 15;
                cp_async16(dB + (uint32_t)(row * BTS + ch * 4) * 4u,
                           Bk + (size_t)row * ldb + ch * 4);
            }
            asm volatile("cp.async.mbarrier.arrive.noinc.shared::cta.b64 [%0];"
                         :: "r"(sbase + 16 * s) : "memory");
        }
    } else {
        // ---- consumers (4 warps, 32x64 block each): ldsm A+B -> cvt A -> mma ----
        const int wr = wid >> 1;              // 0..1 (32 rows each)
        const int wc = wid & 1;               // 0..1 (64 cols each)
        const int gid = lane >> 2, tig = lane & 3;
        const int lmr  = (lane & 7) + ((lane >> 3) & 1) * 8;  // row-in-16 for ldsm
        const int lmk  = ((lane >> 3) >> 1) * 4;              // k-half for ldsm
        const int lm_row  = wr * 32 + lmr;                    // A rows
        const int blm_row = wc * 64 + lmr;                    // B (N-major) rows
        const bool cvtB = (flags & F_CVT_B) != 0;

        float acc[2][8][4];
        #pragma unroll
        for (int mi = 0; mi < 2; ++mi)
            #pragma unroll
            for (int ni = 0; ni < 8; ++ni)
                #pragma unroll
                for (int r = 0; r < 4; ++r) acc[mi][ni][r] = 0.0f;

        uint32_t a[2][2][4], b[2][8][2];

        for (int kt = 0; kt < KT; ++kt) {
            const int s = kt & (NSTAGE - 1);
            mbar_wait(sbase + 16 * s, (uint32_t)((kt >> 1) & 1));

            const uint32_t aBase = dbase + (uint32_t)(s * BUF + lm_row * AS + lmk) * 4u;
            const uint32_t bBase = dbase + (uint32_t)(s * BUF + A_SZ + blm_row * BTS + lmk) * 4u;

            auto load_frag = [&](int kk, int d) {
                #pragma unroll
                for (int mi = 0; mi < 2; ++mi)
                    ldsm_x4(a[d][mi][0], a[d][mi][1], a[d][mi][2], a[d][mi][3],
                            aBase + (uint32_t)(mi * 16 * AS + kk) * 4u);
                // B: 4 ldsm_x4 cover n-groups (2 per ldsm) x both k-halves
                #pragma unroll
                for (int nj = 0; nj < 4; ++nj)
                    ldsm_x4(b[d][2 * nj][0], b[d][2 * nj + 1][0],
                            b[d][2 * nj][1], b[d][2 * nj + 1][1],
                            bBase + (uint32_t)(nj * 16 * BTS + kk) * 4u);
            };

            load_frag(0, 0);
            #pragma unroll
            for (int kq = 0; kq < BK / 8; ++kq) {
                const int d = kq & 1;
                if (kq < BK / 8 - 1) {
                    load_frag((kq + 1) * 8, d ^ 1);
                    if (kq == BK / 8 - 2) {
                        // all smem reads of this tile issued -> release the stage
                        __syncwarp();
                        if (lane == 0) mbar_arrive(sbase + 16 * s + 8);
                    }
                }
                // A fragments: round-to-nearest tf32 (required for accuracy)
                #pragma unroll
                for (int mi = 0; mi < 2; ++mi)
                    #pragma unroll
                    for (int j = 0; j < 4; ++j)
                        a[d][mi][j] = cvt_bits(a[d][mi][j]);
                if (cvtB) {
                    #pragma unroll
                    for (int ni = 0; ni < 8; ++ni) {
                        b[d][ni][0] = cvt_bits(b[d][ni][0]);
                        b[d][ni][1] = cvt_bits(b[d][ni][1]);
                    }
                }
                #pragma unroll
                for (int mi = 0; mi < 2; ++mi)
                    #pragma unroll
                    for (int ni = 0; ni < 8; ++ni)
                        mma_tf32(acc[mi][ni][0], acc[mi][ni][1], acc[mi][ni][2], acc[mi][ni][3],
                                 a[d][mi][0], a[d][mi][1], a[d][mi][2], a[d][mi][3],
                                 b[d][ni][0], b[d][ni][1]);
            }
        }

        // epilogue
        if (flags & F_XT_OUT) {
            // round to tf32 bits + transposed store: C[col*ldc + row]
            #pragma unroll
            for (int mi = 0; mi < 2; ++mi) {
                #pragma unroll
                for (int ni = 0; ni < 8; ++ni) {
                    const int row = m0 + wr * 32 + mi * 16 + gid;
                    const int col = wc * 64 + ni * 8 + tig * 2;
                    C[(size_t)col * ldc + row] =
                        __uint_as_float(f2tf32(acc[mi][ni][0]));
                    C[(size_t)(col + 1) * ldc + row] =
                        __uint_as_float(f2tf32(acc[mi][ni][1]));
                    C[(size_t)col * ldc + row + 8] =
                        __uint_as_float(f2tf32(acc[mi][ni][2]));
                    C[(size_t)(col + 1) * ldc + row + 8] =
                        __uint_as_float(f2tf32(acc[mi][ni][3]));
                }
            }
        } else {
            #pragma unroll
            for (int mi = 0; mi < 2; ++mi) {
                #pragma unroll
                for (int ni = 0; ni < 8; ++ni) {
                    const int row = m0 + wr * 32 + mi * 16 + gid;
                    const int col = wc * 64 + ni * 8 + tig * 2;
                    *(float2*)(C + (size_t)row * ldc + col) =
                        make_float2(acc[mi][ni][0], acc[mi][ni][1]);
                    *(float2*)(C + (size_t)(row + 8) * ldc + col) =
                        make_float2(acc[mi][ni][2], acc[mi][ni][3]);
                }
            }
        }
    }
}

// dst[Cc,R] = src[R,Cc]^T, 32x32 smem tiles, block (32,8), grid (Cc/32, R/32)
__global__ __launch_bounds__(256, 4)
void transpose_k(float* __restrict__ dst, const float* __restrict__ src,
                 int R, int Cc) {
    __shared__ float t[32][33];
    const int c0 = blockIdx.x * 32, r0 = blockIdx.y * 32;
    const int tx = threadIdx.x, ty = threadIdx.y;
    #pragma unroll
    for (int j = 0; j < 32; j += 8)
        t[ty + j][tx] = src[(size_t)(r0 + ty + j) * Cc + c0 + tx];
    __syncthreads();
    #pragma unroll
    for (int j = 0; j < 32; j += 8)
        dst[(size_t)(c0 + ty + j) * R + r0 + tx] = t[tx][ty + j];
}

extern "C" void kernel_launch(void* const* d_in, const int* in_sizes, int n_in,
                              void* d_out, int out_size) {
    const float* inputs  = (const float*)d_in[0];   // [16384, 512]
    const float* adj     = (const float*)d_in[1];   // [16384, 16384]
    const float* weights = (const float*)d_in[2];   // [512, 128]
    float* out = (float*)d_out;                     // [16384, 128]
    (void)in_sizes; (void)n_in; (void)out_size;

    cudaFuncSetAttribute(gemm_ws_tf32,
                         cudaFuncAttributeMaxDynamicSharedMemorySize, SMEM_BYTES);

    float *XT, *WT;
    cudaGetSymbolAddress((void**)&XT, g_XT);
    cudaGetSymbolAddress((void**)&WT, g_WT);

    // W^T [128,512]
    transpose_k<<<dim3(D_OUT / 32, D_IN / 32), dim3(32, 8)>>>(WT, weights, D_IN, D_OUT);
    // G1: X^T = (inputs @ W)^T  (B = W^T raw -> cvtB; rounded transposed store)
    gemm_ws_tf32<<<N_ROWS / BM, NTHREADS, SMEM_BYTES>>>(
        XT, inputs, WT, D_IN, D_IN, D_IN, N_ROWS, F_CVT_B | F_XT_OUT);
    // G2: out = adj @ X  (B = X^T pre-rounded, N-major; normal store)
    gemm_ws_tf32<<<N_ROWS / BM, NTHREADS, SMEM_BYTES>>>(
        out, adj, XT, N_ROWS, N_ROWS, N_ROWS, BN, 0);
}